// round 16
// baseline (speedup 1.0000x reference)
#include <cuda_runtime.h>
#include <cuda_fp16.h>
#include <math.h>
#include <stdint.h>

#define DIMM   2048
#define NHEADS 16
#define HDIM   128
#define SEQL   1024
#define BS     2
#define ALEN   10
#define MAXF   10
#define KCAT   1152   /* 10 adapter + 1024 keys + 118 zero pad = 9*128 */
#define MPAD   (BS*SEQL + 128)   /* 2176: x rows + adapter row tile */
#define QSCALE 0.08838834764831843f

// ---------------- scratch (device globals; no allocation allowed) ----------
__device__ __half g_xh [MPAD*DIMM];          // x (2048) | adapter (10) | zeros
__device__ __half g_wh [3*DIMM*DIMM];        // wq|wk|wv fp16 contiguous
__device__ __half g_woh[DIMM*DIMM];
__device__ __half g_Qh [BS*SEQL*DIMM];       // roped + pre-scaled Q
__device__ __half g_Vh [MPAD*DIMM];          // V fp16 (incl. adapter rows)
__device__ __half g_Kch[BS*NHEADS*KCAT*HDIM];
__device__ __half g_Vth[BS*NHEADS*HDIM*KCAT];   // V transposed: [z][d][k]
__device__ __half g_Oh [BS*SEQL*DIMM];

// ---------------- PTX helpers ----------------------------------------------
__device__ __forceinline__ uint32_t smem_to_u32(const void* p) {
    uint32_t a;
    asm("{ .reg .u64 t; cvta.to.shared.u64 t, %1; cvt.u32.u64 %0, t; }" : "=r"(a) : "l"(p));
    return a;
}
#define CP16(dst, src) \
    asm volatile("cp.async.cg.shared.global [%0], [%1], 16;" :: "r"(dst), "l"(src))
#define CP_COMMIT() asm volatile("cp.async.commit_group;" ::: "memory")
#define CP_WAIT0()  asm volatile("cp.async.wait_group 0;" ::: "memory")
#define CP_WAIT1()  asm volatile("cp.async.wait_group 1;" ::: "memory")
#define CP_WAIT2()  asm volatile("cp.async.wait_group 2;" ::: "memory")

#define LDSM4(r, a) \
    asm volatile("ldmatrix.sync.aligned.m8n8.x4.shared.b16 {%0,%1,%2,%3},[%4];" \
        : "=r"((r)[0]), "=r"((r)[1]), "=r"((r)[2]), "=r"((r)[3]) : "r"(a))

__device__ __forceinline__ void mma16(float* c, const uint32_t* a, uint32_t b0, uint32_t b1) {
    asm volatile(
        "mma.sync.aligned.m16n8k16.row.col.f32.f16.f16.f32 "
        "{%0,%1,%2,%3},{%4,%5,%6,%7},{%8,%9},{%0,%1,%2,%3};"
        : "+f"(c[0]), "+f"(c[1]), "+f"(c[2]), "+f"(c[3])
        : "r"(a[0]), "r"(a[1]), "r"(a[2]), "r"(a[3]), "r"(b0), "r"(b1));
}

// ---------------- fp16 tensor-core batched GEMM: C = A @ B^T ----------------
// CTA tile 128x128, 4 warps (2m x 2n), warp tile 64x64, BK=32, 4-stage cp.async.
// 128 threads; 2 CTAs/SM. 8 LDSM4 per 32 MMAs -> high MMA issue fraction.
#define HG_STAGE 20480
#define HG_SMEM  81920

template <typename OutT, bool FUSE>
__global__ __launch_bounds__(128, 2) void hgemm(
    const __half* __restrict__ A, const __half* __restrict__ B, OutT* __restrict__ C,
    int K, int lda, int ldb, int ldc,
    long long bSh, long long cSh, int nh,
    const float* __restrict__ fc, const float* __restrict__ fs)
{
    const int m0 = blockIdx.y * 128, n0 = blockIdx.x * 128;
    extern __shared__ char smem[];
    const uint32_t sb = smem_to_u32(smem);
    int zh = blockIdx.z % nh;
    B += zh*bSh;
    C += zh*cSh;

    const int tid = threadIdx.x, lane = tid & 31, warp = tid >> 5;
    const int wm = warp & 1, wn = warp >> 1;       // warp tile 64(m) x 64(n)
    const int nch = K >> 5;

    // copy mapping: each of 128 threads owns one row; 4x16B = 64B (full BK row)
    const __half* ag = A + (long long)(m0 + tid) * lda;
    const __half* bg = B + (long long)(n0 + tid) * ldb;
    const uint32_t sa  = sb + tid*80;
    const uint32_t sbb = sb + 10240 + tid*80;

    float acc[4][8][4];
    #pragma unroll
    for (int mi = 0; mi < 4; mi++)
        #pragma unroll
        for (int ni = 0; ni < 8; ni++)
            #pragma unroll
            for (int j = 0; j < 4; j++) acc[mi][ni][j] = 0.f;

    #pragma unroll
    for (int s = 0; s < 3; s++) {
        #pragma unroll
        for (int i = 0; i < 4; i++) {
            CP16(sa  + s*HG_STAGE + i*16, ag + s*32 + i*8);
            CP16(sbb + s*HG_STAGE + i*16, bg + s*32 + i*8);
        }
        CP_COMMIT();
    }

    const int rsel = lane & 15, csel = lane >> 4;

    for (int c = 0; c < nch; c++) {
        CP_WAIT2();
        __syncthreads();

        const uint32_t abase = sb + (c & 3)*HG_STAGE + (wm*64)*80;
        const uint32_t bbase = sb + (c & 3)*HG_STAGE + 10240 + (wn*64)*80;

        uint32_t a[4][4], b[4][4];
        #pragma unroll
        for (int nj = 0; nj < 4; nj++)
            LDSM4(b[nj], bbase + (nj*16 + rsel)*80 + csel*16);
        #pragma unroll
        for (int mi = 0; mi < 4; mi++)
            LDSM4(a[mi], abase + (mi*16 + rsel)*80 + csel*16);

        int nxt = c + 3;
        if (nxt < nch) {
            int s = nxt & 3;
            #pragma unroll
            for (int i = 0; i < 4; i++) {
                CP16(sa  + s*HG_STAGE + i*16, ag + nxt*32 + i*8);
                CP16(sbb + s*HG_STAGE + i*16, bg + nxt*32 + i*8);
            }
        }
        CP_COMMIT();

        // ks = 0
        #pragma unroll
        for (int mi = 0; mi < 4; mi++)
            #pragma unroll
            for (int ni = 0; ni < 8; ni++)
                mma16(acc[mi][ni], a[mi], b[ni>>1][ni&1], b[ni>>1][(ni&1)+2]);
        // fragments for ks = 1 (reuse regs)
        #pragma unroll
        for (int nj = 0; nj < 4; nj++)
            LDSM4(b[nj], bbase + (nj*16 + rsel)*80 + 32 + csel*16);
        #pragma unroll
        for (int mi = 0; mi < 4; mi++)
            LDSM4(a[mi], abase + (mi*16 + rsel)*80 + 32 + csel*16);
        // ks = 1
        #pragma unroll
        for (int mi = 0; mi < 4; mi++)
            #pragma unroll
            for (int ni = 0; ni < 8; ni++)
                mma16(acc[mi][ni], a[mi], b[ni>>1][ni&1], b[ni>>1][(ni&1)+2]);
    }

    const int er = lane >> 2, ec = (lane & 3) * 2;

    if (FUSE) {
        // zh: 0=Q(rope+scale->Qh), 1=K(rope+scatter->Kch), 2=V(->Vh fp16)
        #pragma unroll
        for (int mi = 0; mi < 4; mi++) {
            #pragma unroll
            for (int ni = 0; ni < 8; ni++) {
                int row = m0 + wm*64 + mi*16 + er;
                int col = n0 + wn*64 + ni*8 + ec;
                float* cc = acc[mi][ni];
                int d = col & (HDIM-1), h = col >> 7, p = d >> 1;
                #pragma unroll
                for (int rr = 0; rr < 2; rr++) {
                    int r_ = row + rr*8;
                    float vx = cc[rr*2], vy = cc[rr*2 + 1];
                    if (zh == 2) {
                        *(__half2*)(g_Vh + (long long)r_*DIMM + col) = __floats2half2_rn(vx, vy);
                    } else if (r_ < BS*SEQL) {
                        int q = r_ & (SEQL-1);
                        float cv = fc[q*64 + p], sv = fs[q*64 + p];
                        float ox = vx*cv - vy*sv, oy = vx*sv + vy*cv;
                        if (zh == 0) {
                            *(__half2*)(g_Qh + (long long)r_*DIMM + col) =
                                __floats2half2_rn(ox*QSCALE, oy*QSCALE);
                        } else {
                            int b = r_ >> 10;
                            *(__half2*)(g_Kch +
                                ((long long)(b*NHEADS + h)*KCAT + ALEN + q)*HDIM + d) =
                                __floats2half2_rn(ox, oy);
                        }
                    } else if (zh == 1 && r_ < BS*SEQL + ALEN) {
                        int j = r_ - BS*SEQL;
                        __half2 o = __floats2half2_rn(vx, vy);
                        *(__half2*)(g_Kch + ((long long)h*KCAT + j)*HDIM + d) = o;
                        *(__half2*)(g_Kch + ((long long)(NHEADS + h)*KCAT + j)*HDIM + d) = o;
                    }
                }
            }
        }
        return;
    }

    #pragma unroll
    for (int mi = 0; mi < 4; mi++) {
        #pragma unroll
        for (int ni = 0; ni < 8; ni++) {
            int row = m0 + wm*64 + mi*16 + er;
            int col = n0 + wn*64 + ni*8 + ec;
            float* cc = acc[mi][ni];
            *(float2*)((float*)C + (long long)row * ldc + col) = make_float2(cc[0], cc[1]);
            *(float2*)((float*)C + (long long)(row+8) * ldc + col) = make_float2(cc[2], cc[3]);
        }
    }
}

// ---------------- fused flash attention -------------------------------------
#define FA_PITCH  272                     /* 256B data + 16B pad */
#define FA_K_OFF  17408                   /* 64*272 Q tile */
#define FA_V_OFF  (17408 + 34816)
#define FA_VA_OFF (FA_V_OFF + 34816)      /* 128 x 48B adapter-V block */
#define FA_SMEM   (FA_VA_OFF + 6144)      /* 93184 */

__global__ __launch_bounds__(128, 2) void flash_kernel(
    const float* __restrict__ gate1, const float* __restrict__ gate2,
    const int* __restrict__ vsp)
{
    extern __shared__ char smem[];
    const uint32_t sb = smem_to_u32(smem);
    const int bx = blockIdx.x;
    const int z = bx & 31;
    const int mi = 15 - (bx >> 5);        // heavy tiles first (LPT)
    const int m0 = mi * 64;
    const int b = z >> 4, h = z & 15;
    const int tid = threadIdx.x, lane = tid & 31, warp = tid >> 5;
    const int rsel = lane & 15, csel = lane >> 4;
    const int er = lane >> 2, ec = (lane & 3) * 2;
    const int vs = *vsp;
    const float g2 = gate2[h];

    const __half* Qg = g_Qh + ((long long)(b*SEQL + m0))*DIMM + h*HDIM;
    const __half* Kg = g_Kch + (long long)z*KCAT*HDIM;
    const __half* Vg = g_Vth + (long long)z*HDIM*KCAT;

    {
        int row = tid >> 1, seg = tid & 1;
        const __half* src = Qg + (long long)row*DIMM + seg*64;
        uint32_t dst = sb + row*FA_PITCH + seg*128;
        #pragma unroll
        for (int i = 0; i < 8; i++) CP16(dst + i*16, src + i*8);
    }
    {
        const __half* src = Vg + (long long)tid*KCAT;
        uint32_t dst = sb + FA_VA_OFF + tid*48;
        CP16(dst, src); CP16(dst + 16, src + 8);
    }
    {
        const __half* ks = Kg + tid*HDIM;
        uint32_t kd = sb + FA_K_OFF + tid*FA_PITCH;
        #pragma unroll
        for (int i = 0; i < 16; i++) CP16(kd + i*16, ks + i*8);
        const __half* vsrc = Vg + (long long)tid*KCAT;
        uint32_t vd = sb + FA_V_OFF + tid*FA_PITCH;
        #pragma unroll
        for (int i = 0; i < 16; i++) CP16(vd + i*16, vsrc + i*8);
    }
    CP_COMMIT();

    const int q0 = m0 + warp*16 + er, q1 = q0 + 8;
    const bool grow0 = q0 >= vs + MAXF, grow1 = q1 >= vs + MAXF;

    float oacc[16][4];
    #pragma unroll
    for (int n = 0; n < 16; n++)
        oacc[n][0] = oacc[n][1] = oacc[n][2] = oacc[n][3] = 0.f;
    float m0r = -1e30f, m1r = -1e30f, l0 = 0.f, l1 = 0.f;
    float ad[4], adx[4];

    const int nkt = (m0 + 73)/128 + 1;

    for (int kt = 0; kt < nkt; kt++) {
        if (kt == 0) CP_WAIT0(); else CP_WAIT1();
        __syncthreads();

        float sacc[16][4];
        #pragma unroll
        for (int n = 0; n < 16; n++)
            sacc[n][0] = sacc[n][1] = sacc[n][2] = sacc[n][3] = 0.f;

        #pragma unroll
        for (int kk = 0; kk < 8; kk++) {
            uint32_t a[4], bf[8][4];
            LDSM4(a, sb + (warp*16 + rsel)*FA_PITCH + kk*32 + csel*16);
            #pragma unroll
            for (int nj = 0; nj < 8; nj++)
                LDSM4(bf[nj], sb + FA_K_OFF + (nj*16 + rsel)*FA_PITCH + kk*32 + csel*16);
            #pragma unroll
            for (int ni = 0; ni < 16; ni++)
                mma16(sacc[ni], a, bf[ni>>1][ni&1], bf[ni>>1][(ni&1)+2]);
        }
        __syncthreads();
        if (kt + 1 < nkt) {
            const __half* src = Kg + (long long)(kt+1)*128*HDIM + tid*HDIM;
            uint32_t dst = sb + FA_K_OFF + tid*FA_PITCH;
            #pragma unroll
            for (int i = 0; i < 16; i++) CP16(dst + i*16, src + i*8);
        }
        CP_COMMIT();

        if (kt == 0) {
            #pragma unroll
            for (int j = 0; j < 4; j++) { ad[j] = sacc[0][j]; adx[j] = sacc[1][j]; }
        }

        float mx0 = -1e30f, mx1 = -1e30f;
        #pragma unroll
        for (int ni = 0; ni < 16; ni++) {
            #pragma unroll
            for (int j = 0; j < 4; j++) {
                int kkey = kt*128 + ni*8 + ec + (j & 1) - ALEN;
                int q = (j < 2) ? q0 : q1;
                bool gr = (j < 2) ? grow0 : grow1;
                float s = sacc[ni][j];
                bool val = (kkey >= 0) && (kkey <= q);
                if (val && gr && kkey >= vs && kkey < vs + MAXF) s += g2;
                s = val ? s : -1e30f;
                sacc[ni][j] = s;
                if (j < 2) mx0 = fmaxf(mx0, s); else mx1 = fmaxf(mx1, s);
            }
        }
        mx0 = fmaxf(mx0, __shfl_xor_sync(0xffffffffu, mx0, 1));
        mx0 = fmaxf(mx0, __shfl_xor_sync(0xffffffffu, mx0, 2));
        mx1 = fmaxf(mx1, __shfl_xor_sync(0xffffffffu, mx1, 1));
        mx1 = fmaxf(mx1, __shfl_xor_sync(0xffffffffu, mx1, 2));
        float nm0 = fmaxf(m0r, mx0), nm1 = fmaxf(m1r, mx1);
        float sc0 = __expf(m0r - nm0), sc1 = __expf(m1r - nm1);
        m0r = nm0; m1r = nm1;
        l0 *= sc0; l1 *= sc1;
        #pragma unroll
        for (int n = 0; n < 16; n++) {
            oacc[n][0] *= sc0; oacc[n][1] *= sc0;
            oacc[n][2] *= sc1; oacc[n][3] *= sc1;
        }

        uint32_t pu[16][2];
        float s0 = 0.f, s1 = 0.f;
        #pragma unroll
        for (int ni = 0; ni < 16; ni++) {
            float p0 = __expf(sacc[ni][0] - m0r);
            float p1 = __expf(sacc[ni][1] - m0r);
            float p2 = __expf(sacc[ni][2] - m1r);
            float p3 = __expf(sacc[ni][3] - m1r);
            s0 += p0 + p1; s1 += p2 + p3;
            __half2 h0 = __floats2half2_rn(p0, p1);
            __half2 h1 = __floats2half2_rn(p2, p3);
            pu[ni][0] = *(uint32_t*)&h0;
            pu[ni][1] = *(uint32_t*)&h1;
        }
        s0 += __shfl_xor_sync(0xffffffffu, s0, 1);
        s0 += __shfl_xor_sync(0xffffffffu, s0, 2);
        s1 += __shfl_xor_sync(0xffffffffu, s1, 1);
        s1 += __shfl_xor_sync(0xffffffffu, s1, 2);
        l0 += s0; l1 += s1;

        CP_WAIT1();
        __syncthreads();

        #pragma unroll
        for (int kk = 0; kk < 8; kk++) {
            uint32_t vb[8][4];
            #pragma unroll
            for (int nj = 0; nj < 8; nj++)
                LDSM4(vb[nj], sb + FA_V_OFF + (nj*16 + rsel)*FA_PITCH + kk*32 + csel*16);
            uint32_t ap[4] = { pu[2*kk][0], pu[2*kk][1], pu[2*kk+1][0], pu[2*kk+1][1] };
            #pragma unroll
            for (int ni = 0; ni < 16; ni++)
                mma16(oacc[ni], ap, vb[ni>>1][ni&1], vb[ni>>1][(ni&1)+2]);
        }
        __syncthreads();
        if (kt + 1 < nkt) {
            const __half* src = Vg + (long long)tid*KCAT + (kt+1)*128;
            uint32_t dst = sb + FA_V_OFF + tid*FA_PITCH;
            #pragma unroll
            for (int i = 0; i < 16; i++) CP16(dst + i*16, src + i*8);
        }
        CP_COMMIT();
    }

    float inv0 = 1.f / l0, inv1 = 1.f / l1;
    #pragma unroll
    for (int n = 0; n < 16; n++) {
        oacc[n][0] *= inv0; oacc[n][1] *= inv0;
        oacc[n][2] *= inv1; oacc[n][3] *= inv1;
    }

    {
        float g1t = tanhf(gate1[h]);
        bool hasx = (ec == 0);
        float am0 = fmaxf(ad[0], ad[1]);
        float am1 = fmaxf(ad[2], ad[3]);
        if (hasx) { am0 = fmaxf(am0, fmaxf(adx[0], adx[1]));
                    am1 = fmaxf(am1, fmaxf(adx[2], adx[3])); }
        am0 = fmaxf(am0, __shfl_xor_sync(0xffffffffu, am0, 1));
        am0 = fmaxf(am0, __shfl_xor_sync(0xffffffffu, am0, 2));
        am1 = fmaxf(am1, __shfl_xor_sync(0xffffffffu, am1, 1));
        am1 = fmaxf(am1, __shfl_xor_sync(0xffffffffu, am1, 2));
        float e0 = __expf(ad[0]-am0), e1 = __expf(ad[1]-am0);
        float e2 = __expf(ad[2]-am1), e3 = __expf(ad[3]-am1);
        float x0 = hasx ? __expf(adx[0]-am0) : 0.f, x1 = hasx ? __expf(adx[1]-am0) : 0.f;
        float x2 = hasx ? __expf(adx[2]-am1) : 0.f, x3 = hasx ? __expf(adx[3]-am1) : 0.f;
        float t0 = e0 + e1 + x0 + x1, t1 = e2 + e3 + x2 + x3;
        t0 += __shfl_xor_sync(0xffffffffu, t0, 1);
        t0 += __shfl_xor_sync(0xffffffffu, t0, 2);
        t1 += __shfl_xor_sync(0xffffffffu, t1, 1);
        t1 += __shfl_xor_sync(0xffffffffu, t1, 2);
        float c0 = g1t / t0, c1 = g1t / t1;
        __half2 a0h = __floats2half2_rn(e0*c0, e1*c0);
        __half2 a1h = __floats2half2_rn(e2*c1, e3*c1);
        __half2 a2h = __floats2half2_rn(x0*c0, x1*c0);
        __half2 a3h = __floats2half2_rn(x2*c1, x3*c1);
        uint32_t ap[4] = { *(uint32_t*)&a0h, *(uint32_t*)&a1h,
                           *(uint32_t*)&a2h, *(uint32_t*)&a3h };
        uint32_t vb[8][4];
        #pragma unroll
        for (int nj = 0; nj < 8; nj++)
            LDSM4(vb[nj], sb + FA_VA_OFF + (nj*16 + rsel)*48 + csel*16);
        #pragma unroll
        for (int ni = 0; ni < 16; ni++)
            mma16(oacc[ni], ap, vb[ni>>1][ni&1], vb[ni>>1][(ni&1)+2]);
    }

    long long rbase = (long long)(b*SEQL + m0 + warp*16);
    #pragma unroll
    for (int ni = 0; ni < 16; ni++) {
        int col = h*HDIM + ni*8 + ec;
        *(__half2*)(g_Oh + (rbase + er)*DIMM + col) =
            __floats2half2_rn(oacc[ni][0], oacc[ni][1]);
        *(__half2*)(g_Oh + (rbase + er + 8)*DIMM + col) =
            __floats2half2_rn(oacc[ni][2], oacc[ni][3]);
    }
}

// ---------------- fp32 -> fp16 conversion, 4 float4 per thread (MLP=4) ------
__global__ void f2h_kernel(const float* __restrict__ in, __half* __restrict__ out) {
    int base = blockIdx.x * 1024 + threadIdx.x;
    float4 v[4];
    #pragma unroll
    for (int j = 0; j < 4; j++) v[j] = ((const float4*)in)[base + j*256];
    #pragma unroll
    for (int j = 0; j < 4; j++) {
        int i = base + j*256;
        ((__half2*)out)[2*i]   = __floats2half2_rn(v[j].x, v[j].y);
        ((__half2*)out)[2*i+1] = __floats2half2_rn(v[j].z, v[j].w);
    }
}

__global__ void f2h4_kernel(const float* __restrict__ w0, const float* __restrict__ w1,
                            const float* __restrict__ w2, const float* __restrict__ w3,
                            __half* __restrict__ wh, __half* __restrict__ woh) {
    const float* in;  __half* out;
    switch (blockIdx.y) {
        case 0: in = w0; out = wh; break;
        case 1: in = w1; out = wh + (long long)DIMM*DIMM; break;
        case 2: in = w2; out = wh + 2LL*DIMM*DIMM; break;
        default: in = w3; out = woh; break;
    }
    int base = blockIdx.x * 1024 + threadIdx.x;
    float4 v[4];
    #pragma unroll
    for (int j = 0; j < 4; j++) v[j] = ((const float4*)in)[base + j*256];
    #pragma unroll
    for (int j = 0; j < 4; j++) {
        int i = base + j*256;
        ((__half2*)out)[2*i]   = __floats2half2_rn(v[j].x, v[j].y);
        ((__half2*)out)[2*i+1] = __floats2half2_rn(v[j].z, v[j].w);
    }
}

// ---------------- adapter rows -> xh rows 2048..2175 ------------------------
__global__ void adapter_fill_kernel(const float* __restrict__ adp) {
    int i = blockIdx.x * 256 + threadIdx.x;
    int row = i >> 8;
    int c8 = (i & 255) * 8;
    __half h[8];
    if (row < ALEN) {
        #pragma unroll
        for (int j = 0; j < 8; j++) h[j] = __float2half(adp[row*DIMM + c8 + j]);
    } else {
        #pragma unroll
        for (int j = 0; j < 8; j++) h[j] = __float2half(0.f);
    }
    *(uint4*)(g_xh + (long long)(BS*SEQL + row)*DIMM + c8) = *(uint4*)h;
}

// ---------------- transposed [adapter|values|pad] V (fp16 in) ---------------
__global__ void transpose_v_kernel()
{
    __shared__ float tile[32][33];
    int z = blockIdx.z;
    int b = z >> 4, h = z & 15;
    int kt = blockIdx.x * 32, dt = blockIdx.y * 32;
    int tx = threadIdx.x, ty = threadIdx.y;
    #pragma unroll
    for (int j = 0; j < 4; j++) {
        int k = kt + ty + 8*j;
        int d = dt + tx;
        float v = 0.f;
        if (k < ALEN) v = __half2float(g_Vh[(long long)(BS*SEQL + k)*DIMM + h*HDIM + d]);
        else if (k < ALEN + SEQL)
            v = __half2float(g_Vh[((long long)(b * SEQL + k - ALEN)) * DIMM + h * HDIM + d]);
        tile[ty + 8*j][tx] = v;
    }
    __syncthreads();
    #pragma unroll
    for (int j = 0; j < 4; j++) {
        int d = dt + ty + 8*j;
        g_Vth[((long long)z * HDIM + d) * KCAT + kt + tx] = __float2half(tile[tx][ty + 8*j]);
    }
}

// ---------------- launch -----------------------------------------------------
extern "C" void kernel_launch(void* const* d_in, const int* in_sizes, int n_in,
                              void* d_out, int out_size)
{
    const float* x   = (const float*)d_in[0];
    const float* adp = (const float*)d_in[1];
    /* d_in[2] = mask: equivalent to hard causal mask, recomputed on device */
    const float* fc  = (const float*)d_in[3];
    const float* fs  = (const float*)d_in[4];
    const float* wq  = (const float*)d_in[5];
    const float* wk  = (const float*)d_in[6];
    const float* wv  = (const float*)d_in[7];
    const float* wo  = (const float*)d_in[8];
    const float* g1  = (const float*)d_in[9];
    const float* g2  = (const float*)d_in[10];
    const int*   vsp = (const int*)d_in[11];
    float* out = (float*)d_out;

    __half *xh, *wh, *woh, *Ohp;
    cudaGetSymbolAddress((void**)&xh,  g_xh);
    cudaGetSymbolAddress((void**)&wh,  g_wh);
    cudaGetSymbolAddress((void**)&woh, g_woh);
    cudaGetSymbolAddress((void**)&Ohp, g_Oh);

    cudaFuncSetAttribute((const void*)hgemm<float,true>,  cudaFuncAttributeMaxDynamicSharedMemorySize, HG_SMEM);
    cudaFuncSetAttribute((const void*)hgemm<float,false>, cudaFuncAttributeMaxDynamicSharedMemorySize, HG_SMEM);
    cudaFuncSetAttribute((const void*)flash_kernel, cudaFuncAttributeMaxDynamicSharedMemorySize, FA_SMEM);

    f2h_kernel<<<BS*SEQL*DIMM/4096, 256>>>(x, xh);
    f2h4_kernel<<<dim3(DIMM*DIMM/4096, 4), 256>>>(wq, wk, wv, wo, wh, woh);
    adapter_fill_kernel<<<128, 256>>>(adp);

    // QKV projections fused (M=2176 incl. adapter rows), rope/scatter epilogue
    hgemm<float,true><<<dim3(DIMM/128, MPAD/128, 3), 128, HG_SMEM>>>(
        xh, wh, (float*)Ohp /*unused*/, DIMM, DIMM, DIMM, DIMM,
        (long long)DIMM*DIMM, 0, 3, fc, fs);

    transpose_v_kernel<<<dim3(KCAT/32, HDIM/32, BS*NHEADS), dim3(32, 8)>>>();

    // fused attention: QK + two-segment softmax + PV
    flash_kernel<<<512, 128, FA_SMEM>>>(g1, g2, vsp);

    // output projection: fp32 out to d_out
    hgemm<float,false><<<dim3(DIMM/128, (BS*SEQL)/128, 1), 128, HG_SMEM>>>(
        Ohp, woh, out, DIMM, DIMM, DIMM, DIMM, 0, 0, 1, nullptr, nullptr);
}

// round 17
// speedup vs baseline: 1.3492x; 1.3492x over previous
#include <cuda_runtime.h>
#include <cuda_fp16.h>
#include <math.h>
#include <stdint.h>

#define DIMM   2048
#define NHEADS 16
#define HDIM   128
#define SEQL   1024
#define BS     2
#define ALEN   10
#define MAXF   10
#define KCAT   1152
#define MPAD   (BS*SEQL + 128)   /* 2176: x rows + adapter row tile */
#define QSCALE 0.08838834764831843f

// ---------------- scratch (device globals; no allocation allowed) ----------
__device__ __half g_xh [MPAD*DIMM];          // x (2048) | adapter (10) | zeros
__device__ __half g_wh [3*DIMM*DIMM];        // wq|wk|wv fp16 contiguous
__device__ __half g_woh[DIMM*DIMM];
__device__ __half g_Qh [BS*SEQL*DIMM];       // roped + pre-scaled Q
__device__ __half g_Vh [MPAD*DIMM];          // V fp16 (incl. adapter rows at 2048+)
__device__ __half g_Kch[BS*NHEADS*KCAT*HDIM];
__device__ __half g_Oh [BS*SEQL*DIMM];

// ---------------- PTX helpers ----------------------------------------------
__device__ __forceinline__ uint32_t smem_to_u32(const void* p) {
    uint32_t a;
    asm("{ .reg .u64 t; cvta.to.shared.u64 t, %1; cvt.u32.u64 %0, t; }" : "=r"(a) : "l"(p));
    return a;
}
#define CP16(dst, src) \
    asm volatile("cp.async.cg.shared.global [%0], [%1], 16;" :: "r"(dst), "l"(src))
#define CP_COMMIT() asm volatile("cp.async.commit_group;" ::: "memory")
#define CP_WAIT0()  asm volatile("cp.async.wait_group 0;" ::: "memory")
#define CP_WAIT1()  asm volatile("cp.async.wait_group 1;" ::: "memory")
#define CP_WAIT2()  asm volatile("cp.async.wait_group 2;" ::: "memory")

#define LDSM4(r, a) \
    asm volatile("ldmatrix.sync.aligned.m8n8.x4.shared.b16 {%0,%1,%2,%3},[%4];" \
        : "=r"((r)[0]), "=r"((r)[1]), "=r"((r)[2]), "=r"((r)[3]) : "r"(a))
#define LDSM4T(r, a) \
    asm volatile("ldmatrix.sync.aligned.m8n8.x4.trans.shared.b16 {%0,%1,%2,%3},[%4];" \
        : "=r"((r)[0]), "=r"((r)[1]), "=r"((r)[2]), "=r"((r)[3]) : "r"(a))

__device__ __forceinline__ void mma16(float* c, const uint32_t* a, uint32_t b0, uint32_t b1) {
    asm volatile(
        "mma.sync.aligned.m16n8k16.row.col.f32.f16.f16.f32 "
        "{%0,%1,%2,%3},{%4,%5,%6,%7},{%8,%9},{%0,%1,%2,%3};"
        : "+f"(c[0]), "+f"(c[1]), "+f"(c[2]), "+f"(c[3])
        : "r"(a[0]), "r"(a[1]), "r"(a[2]), "r"(a[3]), "r"(b0), "r"(b1));
}

// ---------------- fp16 tensor-core batched GEMM: C = A @ B^T ----------------
// CTA tile 128x128, 8 warps (2m x 4n), warp tile 64x32, BK=32, 4-stage cp.async.
#define HG_STAGE 20480
#define HG_SMEM  81920

template <typename OutT, bool FUSE>
__global__ __launch_bounds__(256, 2) void hgemm(
    const __half* __restrict__ A, const __half* __restrict__ B, OutT* __restrict__ C,
    int K, int lda, int ldb, int ldc,
    long long bSh, long long cSh, int nh,
    const float* __restrict__ fc, const float* __restrict__ fs)
{
    const int m0 = blockIdx.y * 128, n0 = blockIdx.x * 128;
    extern __shared__ char smem[];
    const uint32_t sb = smem_to_u32(smem);
    int zh = blockIdx.z % nh;
    B += zh*bSh;
    C += zh*cSh;

    const int tid = threadIdx.x, lane = tid & 31, warp = tid >> 5;
    const int wm = warp & 1, wn = warp >> 1;       // warp tile 64(m) x 32(n)
    const int nch = K >> 5;

    const int crow = tid >> 1;
    const int cseg = (tid & 1) * 2;
    const __half* ag = A + (long long)(m0 + crow) * lda + cseg * 8;
    const __half* bg = B + (long long)(n0 + crow) * ldb + cseg * 8;
    const uint32_t sa = sb + crow*80 + cseg*16;
    const uint32_t sbb = sb + 10240 + crow*80 + cseg*16;

    float acc[4][4][4];
    #pragma unroll
    for (int mi = 0; mi < 4; mi++)
        #pragma unroll
        for (int ni = 0; ni < 4; ni++)
            #pragma unroll
            for (int j = 0; j < 4; j++) acc[mi][ni][j] = 0.f;

    #pragma unroll
    for (int s = 0; s < 3; s++) {
        CP16(sa  + s*HG_STAGE,      ag + s*32);
        CP16(sa  + s*HG_STAGE + 16, ag + s*32 + 8);
        CP16(sbb + s*HG_STAGE,      bg + s*32);
        CP16(sbb + s*HG_STAGE + 16, bg + s*32 + 8);
        CP_COMMIT();
    }

    const int rsel = lane & 15, csel = lane >> 4;

    for (int c = 0; c < nch; c++) {
        CP_WAIT2();
        __syncthreads();

        const uint32_t abase = sb + (c & 3)*HG_STAGE + (wm*64)*80;
        const uint32_t bbase = sb + (c & 3)*HG_STAGE + 10240 + (wn*32)*80;

        uint32_t a[4][4], b[2][2][4];
        #pragma unroll
        for (int nj = 0; nj < 2; nj++)
            LDSM4(b[0][nj], bbase + (nj*16 + rsel)*80 + csel*16);
        #pragma unroll
        for (int nj = 0; nj < 2; nj++)
            LDSM4(b[1][nj], bbase + (nj*16 + rsel)*80 + 32 + csel*16);
        #pragma unroll
        for (int mi = 0; mi < 4; mi++)
            LDSM4(a[mi], abase + (mi*16 + rsel)*80 + csel*16);

        int nxt = c + 3;
        if (nxt < nch) {
            int s = nxt & 3;
            CP16(sa  + s*HG_STAGE,      ag + nxt*32);
            CP16(sa  + s*HG_STAGE + 16, ag + nxt*32 + 8);
            CP16(sbb + s*HG_STAGE,      bg + nxt*32);
            CP16(sbb + s*HG_STAGE + 16, bg + nxt*32 + 8);
        }
        CP_COMMIT();

        #pragma unroll
        for (int mi = 0; mi < 4; mi++) {
            #pragma unroll
            for (int ni = 0; ni < 4; ni++)
                mma16(acc[mi][ni], a[mi], b[0][ni>>1][ni&1], b[0][ni>>1][(ni&1)+2]);
            LDSM4(a[mi], abase + (mi*16 + rsel)*80 + 32 + csel*16);
        }
        #pragma unroll
        for (int mi = 0; mi < 4; mi++)
            #pragma unroll
            for (int ni = 0; ni < 4; ni++)
                mma16(acc[mi][ni], a[mi], b[1][ni>>1][ni&1], b[1][ni>>1][(ni&1)+2]);
    }

    const int er = lane >> 2, ec = (lane & 3) * 2;

    if (FUSE) {
        // zh: 0=Q(rope+scale->Qh), 1=K(rope+scatter->Kch), 2=V(->Vh fp16)
        #pragma unroll
        for (int mi = 0; mi < 4; mi++) {
            #pragma unroll
            for (int ni = 0; ni < 4; ni++) {
                int row = m0 + wm*64 + mi*16 + er;
                int col = n0 + wn*32 + ni*8 + ec;
                float* cc = acc[mi][ni];
                int d = col & (HDIM-1), h = col >> 7, p = d >> 1;
                #pragma unroll
                for (int rr = 0; rr < 2; rr++) {
                    int r_ = row + rr*8;
                    float vx = cc[rr*2], vy = cc[rr*2 + 1];
                    if (zh == 2) {
                        *(__half2*)(g_Vh + (long long)r_*DIMM + col) = __floats2half2_rn(vx, vy);
                    } else if (r_ < BS*SEQL) {
                        int q = r_ & (SEQL-1);
                        float cv = fc[q*64 + p], sv = fs[q*64 + p];
                        float ox = vx*cv - vy*sv, oy = vx*sv + vy*cv;
                        if (zh == 0) {
                            *(__half2*)(g_Qh + (long long)r_*DIMM + col) =
                                __floats2half2_rn(ox*QSCALE, oy*QSCALE);
                        } else {
                            int b = r_ >> 10;
                            *(__half2*)(g_Kch +
                                ((long long)(b*NHEADS + h)*KCAT + ALEN + q)*HDIM + d) =
                                __floats2half2_rn(ox, oy);
                        }
                    } else if (zh == 1 && r_ < BS*SEQL + ALEN) {
                        int j = r_ - BS*SEQL;
                        __half2 o = __floats2half2_rn(vx, vy);
                        *(__half2*)(g_Kch + ((long long)h*KCAT + j)*HDIM + d) = o;
                        *(__half2*)(g_Kch + ((long long)(NHEADS + h)*KCAT + j)*HDIM + d) = o;
                    }
                }
            }
        }
        return;
    }

    #pragma unroll
    for (int mi = 0; mi < 4; mi++) {
        #pragma unroll
        for (int ni = 0; ni < 4; ni++) {
            int row = m0 + wm*64 + mi*16 + er;
            int col = n0 + wn*32 + ni*8 + ec;
            float* cc = acc[mi][ni];
            *(float2*)((float*)C + (long long)row * ldc + col) = make_float2(cc[0], cc[1]);
            *(float2*)((float*)C + (long long)(row+8) * ldc + col) = make_float2(cc[2], cc[3]);
        }
    }
}

// ---------------- fused flash attention -------------------------------------
// V loaded token-major straight from g_Vh; PV B-operand via ldmatrix.trans.
#define FA_PITCH  272                     /* 256B data + 16B pad */
#define FA_K_OFF  17408                   /* 64*272 Q tile */
#define FA_V_OFF  (17408 + 34816)
#define FA_VA_OFF (FA_V_OFF + 34816)      /* 16 x 256B adapter-V rows */
#define FA_SMEM   (FA_VA_OFF + 16*FA_PITCH)

__global__ __launch_bounds__(128, 2) void flash_kernel(
    const float* __restrict__ gate1, const float* __restrict__ gate2,
    const int* __restrict__ vsp)
{
    extern __shared__ char smem[];
    const uint32_t sb = smem_to_u32(smem);
    const int bx = blockIdx.x;
    const int z = bx & 31;
    const int mi = 15 - (bx >> 5);        // heavy tiles first (LPT)
    const int m0 = mi * 64;
    const int b = z >> 4, h = z & 15;
    const int tid = threadIdx.x, lane = tid & 31, warp = tid >> 5;
    const int rsel = lane & 15, csel = lane >> 4;
    const int er = lane >> 2, ec = (lane & 3) * 2;
    const int vs = *vsp;
    const float g2 = gate2[h];

    const __half* Qg = g_Qh + ((long long)(b*SEQL + m0))*DIMM + h*HDIM;
    const __half* Kg = g_Kch + (long long)z*KCAT*HDIM;
    const __half* Vb = g_Vh + h*HDIM;     // row-indexed per token / adapter

    // prologue: Q tile, adapter-V rows, K0, V0 (one commit group)
    {
        int row = tid >> 1, seg = tid & 1;
        const __half* src = Qg + (long long)row*DIMM + seg*64;
        uint32_t dst = sb + row*FA_PITCH + seg*128;
        #pragma unroll
        for (int i = 0; i < 8; i++) CP16(dst + i*16, src + i*8);
    }
    if (tid < 32) {                        // adapter V rows 0..15 (k-major)
        int row = tid >> 1, seg = tid & 1;
        const __half* src = Vb + (long long)(BS*SEQL + row)*DIMM + seg*64;
        uint32_t dst = sb + FA_VA_OFF + row*FA_PITCH + seg*128;
        #pragma unroll
        for (int i = 0; i < 8; i++) CP16(dst + i*16, src + i*8);
    }
    {
        const __half* ks = Kg + tid*HDIM;
        uint32_t kd = sb + FA_K_OFF + tid*FA_PITCH;
        #pragma unroll
        for (int i = 0; i < 16; i++) CP16(kd + i*16, ks + i*8);
        // V tile 0: concat rows 0..127 -> adapter rows (<10) or tokens 0..117
        long long vrow = (tid < ALEN) ? (long long)(BS*SEQL + tid)
                                      : (long long)(b*SEQL + tid - ALEN);
        const __half* vsrc = Vb + vrow*DIMM;
        uint32_t vd = sb + FA_V_OFF + tid*FA_PITCH;
        #pragma unroll
        for (int i = 0; i < 16; i++) CP16(vd + i*16, vsrc + i*8);
    }
    CP_COMMIT();

    const int q0 = m0 + warp*16 + er, q1 = q0 + 8;
    const bool grow0 = q0 >= vs + MAXF, grow1 = q1 >= vs + MAXF;

    float oacc[16][4];
    #pragma unroll
    for (int n = 0; n < 16; n++)
        oacc[n][0] = oacc[n][1] = oacc[n][2] = oacc[n][3] = 0.f;
    float m0r = -1e30f, m1r = -1e30f, l0 = 0.f, l1 = 0.f;
    float ad[4], adx[4];

    const int nkt = (m0 + 73)/128 + 1;

    for (int kt = 0; kt < nkt; kt++) {
        if (kt == 0) CP_WAIT0(); else CP_WAIT1();
        __syncthreads();

        float sacc[16][4];
        #pragma unroll
        for (int n = 0; n < 16; n++)
            sacc[n][0] = sacc[n][1] = sacc[n][2] = sacc[n][3] = 0.f;

        // S = Q @ K_tile^T
        #pragma unroll
        for (int kk = 0; kk < 8; kk++) {
            uint32_t a[4], bf[8][4];
            LDSM4(a, sb + (warp*16 + rsel)*FA_PITCH + kk*32 + csel*16);
            #pragma unroll
            for (int nj = 0; nj < 8; nj++)
                LDSM4(bf[nj], sb + FA_K_OFF + (nj*16 + rsel)*FA_PITCH + kk*32 + csel*16);
            #pragma unroll
            for (int ni = 0; ni < 16; ni++)
                mma16(sacc[ni], a, bf[ni>>1][ni&1], bf[ni>>1][(ni&1)+2]);
        }
        __syncthreads();
        if (kt + 1 < nkt) {                    // prefetch K[kt+1]
            const __half* src = Kg + (long long)(kt+1)*128*HDIM + tid*HDIM;
            uint32_t dst = sb + FA_K_OFF + tid*FA_PITCH;
            #pragma unroll
            for (int i = 0; i < 16; i++) CP16(dst + i*16, src + i*8);
        }
        CP_COMMIT();

        if (kt == 0) {
            #pragma unroll
            for (int j = 0; j < 4; j++) { ad[j] = sacc[0][j]; adx[j] = sacc[1][j]; }
        }

        float mx0 = -1e30f, mx1 = -1e30f;
        #pragma unroll
        for (int ni = 0; ni < 16; ni++) {
            #pragma unroll
            for (int j = 0; j < 4; j++) {
                int kkey = kt*128 + ni*8 + ec + (j & 1) - ALEN;
                int q = (j < 2) ? q0 : q1;
                bool gr = (j < 2) ? grow0 : grow1;
                float s = sacc[ni][j];
                bool val = (kkey >= 0) && (kkey <= q);
                if (val && gr && kkey >= vs && kkey < vs + MAXF) s += g2;
                s = val ? s : -1e30f;
                sacc[ni][j] = s;
                if (j < 2) mx0 = fmaxf(mx0, s); else mx1 = fmaxf(mx1, s);
            }
        }
        mx0 = fmaxf(mx0, __shfl_xor_sync(0xffffffffu, mx0, 1));
        mx0 = fmaxf(mx0, __shfl_xor_sync(0xffffffffu, mx0, 2));
        mx1 = fmaxf(mx1, __shfl_xor_sync(0xffffffffu, mx1, 1));
        mx1 = fmaxf(mx1, __shfl_xor_sync(0xffffffffu, mx1, 2));
        float nm0 = fmaxf(m0r, mx0), nm1 = fmaxf(m1r, mx1);
        float sc0 = __expf(m0r - nm0), sc1 = __expf(m1r - nm1);
        m0r = nm0; m1r = nm1;
        l0 *= sc0; l1 *= sc1;
        #pragma unroll
        for (int n = 0; n < 16; n++) {
            oacc[n][0] *= sc0; oacc[n][1] *= sc0;
            oacc[n][2] *= sc1; oacc[n][3] *= sc1;
        }

        uint32_t pu[16][2];
        float s0 = 0.f, s1 = 0.f;
        #pragma unroll
        for (int ni = 0; ni < 16; ni++) {
            float p0 = __expf(sacc[ni][0] - m0r);
            float p1 = __expf(sacc[ni][1] - m0r);
            float p2 = __expf(sacc[ni][2] - m1r);
            float p3 = __expf(sacc[ni][3] - m1r);
            s0 += p0 + p1; s1 += p2 + p3;
            __half2 h0 = __floats2half2_rn(p0, p1);
            __half2 h1 = __floats2half2_rn(p2, p3);
            pu[ni][0] = *(uint32_t*)&h0;
            pu[ni][1] = *(uint32_t*)&h1;
        }
        s0 += __shfl_xor_sync(0xffffffffu, s0, 1);
        s0 += __shfl_xor_sync(0xffffffffu, s0, 2);
        s1 += __shfl_xor_sync(0xffffffffu, s1, 1);
        s1 += __shfl_xor_sync(0xffffffffu, s1, 2);
        l0 += s0; l1 += s1;

        CP_WAIT1();                            // V[kt] ready
        __syncthreads();

        // O += P @ V_tile  (V token-major, ldmatrix.trans B fragments)
        #pragma unroll
        for (int kk = 0; kk < 8; kk++) {
            uint32_t vb[8][4];
            #pragma unroll
            for (int nj = 0; nj < 8; nj++)
                LDSM4T(vb[nj], sb + FA_V_OFF + (kk*16 + rsel)*FA_PITCH + nj*32 + csel*16);
            uint32_t ap[4] = { pu[2*kk][0], pu[2*kk][1], pu[2*kk+1][0], pu[2*kk+1][1] };
            #pragma unroll
            for (int ni = 0; ni < 16; ni++)
                mma16(oacc[ni], ap, vb[ni>>1][(ni&1)*2], vb[ni>>1][(ni&1)*2+1]);
        }
        __syncthreads();
        if (kt + 1 < nkt) {                    // prefetch V[kt+1] (all rows tokens)
            int p = (kt+1)*128 + tid - ALEN;
            if (p > SEQL-1) p = SEQL-1;        // masked tail: value irrelevant
            const __half* src = Vb + (long long)(b*SEQL + p)*DIMM;
            uint32_t dst = sb + FA_V_OFF + tid*FA_PITCH;
            #pragma unroll
            for (int i = 0; i < 16; i++) CP16(dst + i*16, src + i*8);
        }
        CP_COMMIT();
    }

    float inv0 = 1.f / l0, inv1 = 1.f / l1;
    #pragma unroll
    for (int n = 0; n < 16; n++) {
        oacc[n][0] *= inv0; oacc[n][1] *= inv0;
        oacc[n][2] *= inv1; oacc[n][3] *= inv1;
    }

    // adapter segment: separate softmax * tanh(gate1[h]) + one k16 MMA
    {
        float g1t = tanhf(gate1[h]);
        bool hasx = (ec == 0);
        float am0 = fmaxf(ad[0], ad[1]);
        float am1 = fmaxf(ad[2], ad[3]);
        if (hasx) { am0 = fmaxf(am0, fmaxf(adx[0], adx[1]));
                    am1 = fmaxf(am1, fmaxf(adx[2], adx[3])); }
        am0 = fmaxf(am0, __shfl_xor_sync(0xffffffffu, am0, 1));
        am0 = fmaxf(am0, __shfl_xor_sync(0xffffffffu, am0, 2));
        am1 = fmaxf(am1, __shfl_xor_sync(0xffffffffu, am1, 1));
        am1 = fmaxf(am1, __shfl_xor_sync(0xffffffffu, am1, 2));
        float e0 = __expf(ad[0]-am0), e1 = __expf(ad[1]-am0);
        float e2 = __expf(ad[2]-am1), e3 = __expf(ad[3]-am1);
        float x0 = hasx ? __expf(adx[0]-am0) : 0.f, x1 = hasx ? __expf(adx[1]-am0) : 0.f;
        float x2 = hasx ? __expf(adx[2]-am1) : 0.f, x3 = hasx ? __expf(adx[3]-am1) : 0.f;
        float t0 = e0 + e1 + x0 + x1, t1 = e2 + e3 + x2 + x3;
        t0 += __shfl_xor_sync(0xffffffffu, t0, 1);
        t0 += __shfl_xor_sync(0xffffffffu, t0, 2);
        t1 += __shfl_xor_sync(0xffffffffu, t1, 1);
        t1 += __shfl_xor_sync(0xffffffffu, t1, 2);
        float c0 = g1t / t0, c1 = g1t / t1;
        __half2 a0h = __floats2half2_rn(e0*c0, e1*c0);
        __half2 a1h = __floats2half2_rn(e2*c1, e3*c1);
        __half2 a2h = __floats2half2_rn(x0*c0, x1*c0);
        __half2 a3h = __floats2half2_rn(x2*c1, x3*c1);
        uint32_t ap[4] = { *(uint32_t*)&a0h, *(uint32_t*)&a1h,
                           *(uint32_t*)&a2h, *(uint32_t*)&a3h };
        uint32_t vb[8][4];
        #pragma unroll
        for (int nj = 0; nj < 8; nj++)
            LDSM4T(vb[nj], sb + FA_VA_OFF + rsel*FA_PITCH + nj*32 + csel*16);
        #pragma unroll
        for (int ni = 0; ni < 16; ni++)
            mma16(oacc[ni], ap, vb[ni>>1][(ni&1)*2], vb[ni>>1][(ni&1)*2+1]);
    }

    long long rbase = (long long)(b*SEQL + m0 + warp*16);
    #pragma unroll
    for (int ni = 0; ni < 16; ni++) {
        int col = h*HDIM + ni*8 + ec;
        *(__half2*)(g_Oh + (rbase + er)*DIMM + col) =
            __floats2half2_rn(oacc[ni][0], oacc[ni][1]);
        *(__half2*)(g_Oh + (rbase + er + 8)*DIMM + col) =
            __floats2half2_rn(oacc[ni][2], oacc[ni][3]);
    }
}

// ---------------- fp32 -> fp16 conversions, 5 tensors in one launch ---------
__global__ void f2h5_kernel(const float* __restrict__ w0, const float* __restrict__ w1,
                            const float* __restrict__ w2, const float* __restrict__ w3,
                            const float* __restrict__ x,
                            __half* __restrict__ wh, __half* __restrict__ woh,
                            __half* __restrict__ xh) {
    const float* in;  __half* out;
    switch (blockIdx.y) {
        case 0: in = w0; out = wh; break;
        case 1: in = w1; out = wh + (long long)DIMM*DIMM; break;
        case 2: in = w2; out = wh + 2LL*DIMM*DIMM; break;
        case 3: in = w3; out = woh; break;
        default: in = x; out = xh; break;
    }
    int base = blockIdx.x * 1024 + threadIdx.x;
    float4 v[4];
    #pragma unroll
    for (int j = 0; j < 4; j++) v[j] = ((const float4*)in)[base + j*256];
    #pragma unroll
    for (int j = 0; j < 4; j++) {
        int i = base + j*256;
        ((__half2*)out)[2*i]   = __floats2half2_rn(v[j].x, v[j].y);
        ((__half2*)out)[2*i+1] = __floats2half2_rn(v[j].z, v[j].w);
    }
}

// ---------------- adapter rows -> xh rows 2048..2175 ------------------------
__global__ void adapter_fill_kernel(const float* __restrict__ adp) {
    int i = blockIdx.x * 256 + threadIdx.x;
    int row = i >> 8;
    int c8 = (i & 255) * 8;
    __half h[8];
    if (row < ALEN) {
        #pragma unroll
        for (int j = 0; j < 8; j++) h[j] = __float2half(adp[row*DIMM + c8 + j]);
    } else {
        #pragma unroll
        for (int j = 0; j < 8; j++) h[j] = __float2half(0.f);
    }
    *(uint4*)(g_xh + (long long)(BS*SEQL + row)*DIMM + c8) = *(uint4*)h;
}

// ---------------- launch -----------------------------------------------------
extern "C" void kernel_launch(void* const* d_in, const int* in_sizes, int n_in,
                              void* d_out, int out_size)
{
    const float* x   = (const float*)d_in[0];
    const float* adp = (const float*)d_in[1];
    /* d_in[2] = mask: equivalent to hard causal mask, recomputed on device */
    const float* fc  = (const float*)d_in[3];
    const float* fs  = (const float*)d_in[4];
    const float* wq  = (const float*)d_in[5];
    const float* wk  = (const float*)d_in[6];
    const float* wv  = (const float*)d_in[7];
    const float* wo  = (const float*)d_in[8];
    const float* g1  = (const float*)d_in[9];
    const float* g2  = (const float*)d_in[10];
    const int*   vsp = (const int*)d_in[11];
    float* out = (float*)d_out;

    __half *xh, *wh, *woh, *Ohp;
    cudaGetSymbolAddress((void**)&xh,  g_xh);
    cudaGetSymbolAddress((void**)&wh,  g_wh);
    cudaGetSymbolAddress((void**)&woh, g_woh);
    cudaGetSymbolAddress((void**)&Ohp, g_Oh);

    cudaFuncSetAttribute((const void*)hgemm<float,true>,  cudaFuncAttributeMaxDynamicSharedMemorySize, HG_SMEM);
    cudaFuncSetAttribute((const void*)hgemm<float,false>, cudaFuncAttributeMaxDynamicSharedMemorySize, HG_SMEM);
    cudaFuncSetAttribute((const void*)flash_kernel, cudaFuncAttributeMaxDynamicSharedMemorySize, FA_SMEM);

    f2h5_kernel<<<dim3(DIMM*DIMM/4096, 5), 256>>>(wq, wk, wv, wo, x, wh, woh, xh);
    adapter_fill_kernel<<<128, 256>>>(adp);

    // QKV projections fused (M=2176 incl. adapter rows), rope/scatter epilogue
    hgemm<float,true><<<dim3(DIMM/128, MPAD/128, 3), 256, HG_SMEM>>>(
        xh, wh, (float*)Ohp /*unused*/, DIMM, DIMM, DIMM, DIMM,
        (long long)DIMM*DIMM, 0, 3, fc, fs);

    // fused attention: QK + two-segment softmax + PV (V direct from g_Vh)
    flash_kernel<<<512, 128, FA_SMEM>>>(g1, g2, vsp);

    // output projection: fp32 out to d_out
    hgemm<float,false><<<dim3(DIMM/128, (BS*SEQL)/128, 1), 256, HG_SMEM>>>(
        Ohp, woh, out, DIMM, DIMM, DIMM, DIMM, 0, 0, 1, nullptr, nullptr);
}